// round 15
// baseline (speedup 1.0000x reference)
#include <cuda_runtime.h>
#include <math.h>

#define B_DIM 64
#define T_DIM 1000
#define P_ORD 10
#define NFRAMES (B_DIM * T_DIM)
#define PI_D 3.14159265358979323846
#define FULLMASK 0xffffffffu

__device__ double d_M[121];
__device__ float d_x0[20];

// ---- packed f32x2 helpers (sm_100+) ----
typedef unsigned long long u64;
__device__ __forceinline__ u64 pk2(float lo, float hi) {
    u64 r; asm("mov.b64 %0, {%1, %2};" : "=l"(r) : "f"(lo), "f"(hi)); return r;
}
__device__ __forceinline__ u64 add2(u64 a, u64 b) {
    u64 r; asm("add.rn.f32x2 %0, %1, %2;" : "=l"(r) : "l"(a), "l"(b)); return r;
}
__device__ __forceinline__ u64 mul2(u64 a, u64 b) {
    u64 r; asm("mul.rn.f32x2 %0, %1, %2;" : "=l"(r) : "l"(a), "l"(b)); return r;
}
__device__ __forceinline__ u64 fma2(u64 a, u64 b, u64 c) {
    u64 r; asm("fma.rn.f32x2 %0, %1, %2, %3;" : "=l"(r) : "l"(a), "l"(b), "l"(c)); return r;
}
__device__ __forceinline__ float lo2(u64 v) { return __uint_as_float((unsigned)v); }
__device__ __forceinline__ float hi2(u64 v) { return __uint_as_float((unsigned)(v >> 32)); }
#define NEG1_2  0xBF800000BF800000ULL   /* (-1,-1) */
#define EYE_LO2 0x000000003F800000ULL   /* (1, 0)  */
#define EYE_HI2 0x3F80000000000000ULL   /* (0, 1)  */
// exact subtraction a-b via single-rounded fma(b, -1, a)
__device__ __forceinline__ u64 sub2(u64 a, u64 b) { return fma2(b, NEG1_2, a); }

// Parallel init: one block per matrix entry (j,d); threads split the k-sum.
__global__ void init_consts_kernel() {
    __shared__ double red[128];
    int e = blockIdx.x;
    int j = e / 11, d = e % 11;
    int k = threadIdx.x;

    double term = 0.0;
    if (k >= 1 && k <= 114) {
        double gd = (d == 0) ? 1.0 : 2.0 * cos(2.0 * PI_D * (double)k * (double)d / 512.0);
        term = 2.0 * gd * cos(2.0 * PI_D * (double)k * (double)j / 230.0);
    }
    red[threadIdx.x] = term;
    __syncthreads();
#pragma unroll
    for (int s = 64; s > 0; s >>= 1) {
        if (threadIdx.x < s) red[threadIdx.x] += red[threadIdx.x + s];
        __syncthreads();
    }
    if (threadIdx.x == 0) {
        double s = red[0];
        s += (d == 0) ? 1.0 : 2.0;                               // k = 0 bin
        double g115 = (d == 0) ? 1.0 : 2.0 * cos(2.0 * PI_D * 115.0 * (double)d / 512.0);
        s += ((j & 1) ? -1.0 : 1.0) * g115;                      // k = 115 Nyquist
        d_M[e] = s / 230.0;
    }
    if (e == 0 && threadIdx.x == 127) {
        double cr = 1.0, ci = 0.0;
        for (int p = 0; p < 10; p++) {
            double nr = cr * 0.4 - ci * 0.9;
            double ni = cr * 0.9 + ci * 0.4;
            cr = nr; ci = ni;
            d_x0[p]      = (float)nr;
            d_x0[10 + p] = (float)ni;
        }
    }
}

// Smith complex division with approx divides + __divsc3-style recovery.
__device__ __forceinline__ void cdivf(float a, float b, float c, float d,
                                      float& outr, float& outi) {
    float re, im;
    if (fabsf(c) >= fabsf(d)) {
        float r     = __fdividef(d, c);
        float denom = __fmaf_rn(d, r, c);
        float inv;  asm("rcp.approx.f32 %0, %1;" : "=f"(inv) : "f"(denom));
        re = __fmul_rn(__fmaf_rn(b, r, a), inv);
        im = __fmul_rn(__fmaf_rn(-a, r, b), inv);
    } else {
        float r     = __fdividef(c, d);
        float denom = __fmaf_rn(c, r, d);
        float inv;  asm("rcp.approx.f32 %0, %1;" : "=f"(inv) : "f"(denom));
        re = __fmul_rn(__fmaf_rn(a, r, b), inv);
        im = __fmul_rn(__fmaf_rn(b, r, -a), inv);
    }
    if (isnan(re) && isnan(im)) {
        if ((c == 0.0f && d == 0.0f) && (!isnan(a) || !isnan(b))) {
            re = copysignf(INFINITY, c) * a;
            im = copysignf(INFINITY, c) * b;
        } else if ((isinf(a) || isinf(b)) && isfinite(c) && isfinite(d)) {
            float aa = copysignf(isinf(a) ? 1.0f : 0.0f, a);
            float bb = copysignf(isinf(b) ? 1.0f : 0.0f, b);
            re = INFINITY * __fadd_rn(__fmul_rn(aa, c), __fmul_rn(bb, d));
            im = INFINITY * __fsub_rn(__fmul_rn(bb, c), __fmul_rn(aa, d));
        } else if ((isinf(c) || isinf(d)) && isfinite(a) && isfinite(b)) {
            float cc = copysignf(isinf(c) ? 1.0f : 0.0f, c);
            float dd = copysignf(isinf(d) ? 1.0f : 0.0f, d);
            re = 0.0f * __fadd_rn(__fmul_rn(a, cc), __fmul_rn(b, dd));
            im = 0.0f * __fsub_rn(__fmul_rn(b, cc), __fmul_rn(a, dd));
        }
    }
    outr = re; outi = im;
}

// One thread per frame: fp64 front-end, then DK with all 10 roots
// as 5 packed f32x2 pairs. No shuffles. Warp-level bitwise-fixpoint exit.
__global__ void __launch_bounds__(128)
formant_kernel(const float* __restrict__ in, float* __restrict__ out) {
    __shared__ double sM[121];
    __shared__ float sX0[20];
    if (threadIdx.x < 121) sM[threadIdx.x] = d_M[threadIdx.x];
    if (threadIdx.x < 20)  sX0[threadIdx.x] = d_x0[threadIdx.x];
    __syncthreads();

    int frame = blockIdx.x * 128 + threadIdx.x;
    int b = frame / T_DIM;
    int t = frame - b * T_DIM;
    const float* base = in + (size_t)b * (P_ORD * T_DIM) + t;

    // ======== FRONT-END (fp64, every thread = one frame) ========
    float pc[11];
    {
        double A[11];
        A[0] = 1.0;
        {
            double a[10];
            a[0] = (double)base[0];
#pragma unroll
            for (int p = 1; p < 10; p++) {
                double k = (double)base[p * T_DIM];
                double na[10];
#pragma unroll
                for (int i = 0; i < p; i++) na[i] = a[i] + k * a[p - 1 - i];
#pragma unroll
                for (int i = 0; i < p; i++) a[i] = na[i];
                a[p] = k;
            }
#pragma unroll
            for (int i = 0; i < 10; i++) A[i + 1] = a[i];
        }

        double c[11];
#pragma unroll
        for (int d = 0; d < 11; d++) {
            double s = 0.0;
#pragma unroll
            for (int n = 0; n < 11 - d; n++) s = fma(A[n], A[n + d], s);
            c[d] = s;
        }

        double r[11];
#pragma unroll
        for (int j = 0; j < 11; j++) {
            double s = 0.0;
#pragma unroll
            for (int d = 0; d < 11; d++) s = fma(sM[j * 11 + d], c[d], s);
            r[j] = s;
        }

        pc[0] = 1.0f;
        {
            double a[10];
            double k0 = -r[1] / r[0];
            a[0] = k0;
            double err = r[0] * (1.0 - k0 * k0);
#pragma unroll
            for (int m = 1; m < 10; m++) {
                double acc = r[m + 1];
#pragma unroll
                for (int i = 0; i < m; i++) acc = fma(a[i], r[m - i], acc);
                double k = -acc / err;
                double na[10];
#pragma unroll
                for (int i = 0; i < m; i++) na[i] = a[i] + k * a[m - 1 - i];
#pragma unroll
                for (int i = 0; i < m; i++) a[i] = na[i];
                a[m] = k;
                err *= (1.0 - k * k);
            }
#pragma unroll
            for (int i = 0; i < 10; i++) pc[i + 1] = (float)a[i];
        }
    }

    // ======== DURAND-KERNER: 10 roots = 5 packed f32x2 pairs ========
    float xr[10], xi[10];
#pragma unroll
    for (int i = 0; i < 10; i++) {
        xr[i] = sX0[i];
        xi[i] = sX0[10 + i];
    }

#pragma unroll 1
    for (int it = 0; it < 30; it++) {
        // pack state: pair p holds roots (2p, 2p+1)
        u64 PX[5], PY[5];
#pragma unroll
        for (int p = 0; p < 5; p++) {
            PX[p] = pk2(xr[2 * p], xr[2 * p + 1]);
            PY[p] = pk2(xi[2 * p], xi[2 * p + 1]);
        }

        // ---- Horner polyval for all 5 pairs (first step folded) ----
        u64 yrP[5], yiP[5];
        {
            u64 c1 = pk2(pc[1], pc[1]);
#pragma unroll
            for (int p = 0; p < 5; p++) { yrP[p] = add2(PX[p], c1); yiP[p] = PY[p]; }
        }
#pragma unroll
        for (int m = 2; m <= 10; m++) {
            u64 cm = pk2(pc[m], pc[m]);
#pragma unroll
            for (int p = 0; p < 5; p++) {
                u64 tr = fma2(mul2(yiP[p], PY[p]), NEG1_2, fma2(yrP[p], PX[p], cm));
                yiP[p] = fma2(yrP[p], PY[p], mul2(yiP[p], PX[p]));
                yrP[p] = tr;
            }
        }

        // ---- denominator product over all 10 roots; eye on own diagonal ----
        u64 drP[5], diP[5];
#pragma unroll
        for (int j = 0; j < 10; j++) {
            u64 R2 = pk2(xr[j], xr[j]);
            u64 I2 = pk2(xi[j], xi[j]);
#pragma unroll
            for (int p = 0; p < 5; p++) {
                u64 er = sub2(PX[p], R2);
                if (j == 2 * p)     er = add2(er, EYE_LO2);
                if (j == 2 * p + 1) er = add2(er, EYE_HI2);
                u64 ei = sub2(PY[p], I2);
                if (j == 0) {
                    drP[p] = er; diP[p] = ei;
                } else {
                    u64 tr = fma2(mul2(diP[p], ei), NEG1_2, mul2(drP[p], er));
                    diP[p] = fma2(drP[p], ei, mul2(diP[p], er));
                    drP[p] = tr;
                }
            }
        }

        // ---- per-root Smith division + update + fixpoint check ----
        bool same = true;
#pragma unroll
        for (int p = 0; p < 5; p++) {
            float ys[2]  = { lo2(yrP[p]), hi2(yrP[p]) };
            float yis[2] = { lo2(yiP[p]), hi2(yiP[p]) };
            float ds[2]  = { lo2(drP[p]), hi2(drP[p]) };
            float dis[2] = { lo2(diP[p]), hi2(diP[p]) };
#pragma unroll
            for (int s = 0; s < 2; s++) {
                int i = 2 * p + s;
                float dr = __fadd_rn(ds[s], 1e-12f);
                float qr, qi;
                cdivf(ys[s], yis[s], dr, dis[s], qr, qi);
                float nx = __fsub_rn(xr[i], qr);
                float ny = __fsub_rn(xi[i], qi);
                same = same && (__float_as_int(nx) == __float_as_int(xr[i]))
                            && (__float_as_int(ny) == __float_as_int(xi[i]));
                xr[i] = nx; xi[i] = ny;
            }
        }
        // Warp-level bitwise fixpoint: all 32 frames unchanged -> remaining
        // iterations are provably no-ops for the whole warp.
        if (__all_sync(FULLMASK, same)) break;
    }

    // ---- roots -> formants, sort, normalize, write ----
    float f[10];
#pragma unroll
    for (int i = 0; i < 10; i++) {
        float fr = atan2f(xi[i], xr[i]) * (10000.0f / (2.0f * (float)PI_D));
        bool valid = (xi[i] > 0.f) && (fr > 50.0f) && (fr < 4950.0f);
        f[i] = valid ? fr : 10000.0f;
    }
#pragma unroll
    for (int pass = 0; pass < 9; pass++) {
#pragma unroll
        for (int i = 0; i < 9; i++) {
            float lo = fminf(f[i], f[i + 1]);
            float hi = fmaxf(f[i], f[i + 1]);
            f[i] = lo; f[i + 1] = hi;
        }
    }

    float* ob = out + (size_t)b * (4 * T_DIM) + t;
#pragma unroll
    for (int q = 0; q < 4; q++)
        ob[q * T_DIM] = 2.0f * f[q] / 11025.0f - 1.0f;
}

extern "C" void kernel_launch(void* const* d_in, const int* in_sizes, int n_in,
                              void* d_out, int out_size) {
    const float* in = (const float*)d_in[0];
    float* out = (float*)d_out;
    (void)in_sizes; (void)n_in; (void)out_size;

    init_consts_kernel<<<121, 128>>>();
    formant_kernel<<<NFRAMES / 128, 128>>>(in, out);
}

// round 16
// speedup vs baseline: 1.3207x; 1.3207x over previous
#include <cuda_runtime.h>
#include <math.h>

#define B_DIM 64
#define T_DIM 1000
#define P_ORD 10
#define NFRAMES (B_DIM * T_DIM)
#define PI_D 3.14159265358979323846
#define FULLMASK 0xffffffffu

__device__ double d_M[121];
__device__ float d_x0[20];

// ---- packed f32x2 helpers (sm_100+) ----
typedef unsigned long long u64;
__device__ __forceinline__ u64 pk2(float lo, float hi) {
    u64 r; asm("mov.b64 %0, {%1, %2};" : "=l"(r) : "f"(lo), "f"(hi)); return r;
}
__device__ __forceinline__ u64 add2(u64 a, u64 b) {
    u64 r; asm("add.rn.f32x2 %0, %1, %2;" : "=l"(r) : "l"(a), "l"(b)); return r;
}
__device__ __forceinline__ u64 mul2(u64 a, u64 b) {
    u64 r; asm("mul.rn.f32x2 %0, %1, %2;" : "=l"(r) : "l"(a), "l"(b)); return r;
}
__device__ __forceinline__ u64 fma2(u64 a, u64 b, u64 c) {
    u64 r; asm("fma.rn.f32x2 %0, %1, %2, %3;" : "=l"(r) : "l"(a), "l"(b), "l"(c)); return r;
}
__device__ __forceinline__ float lo2(u64 v) { return __uint_as_float((unsigned)v); }
__device__ __forceinline__ float hi2(u64 v) { return __uint_as_float((unsigned)(v >> 32)); }
__device__ __forceinline__ float rcpa(float x) {
    float r; asm("rcp.approx.f32 %0, %1;" : "=f"(r) : "f"(x)); return r;
}
#define NEG1_2  0xBF800000BF800000ULL   /* (-1,-1) */
#define EYE_LO2 0x000000003F800000ULL   /* (1, 0)  */
#define EYE_HI2 0x3F80000000000000ULL   /* (0, 1)  */
// exact subtraction a-b via single-rounded fma(b, -1, a)
__device__ __forceinline__ u64 sub2(u64 a, u64 b) { return fma2(b, NEG1_2, a); }

// Parallel init: one block per matrix entry (j,d); threads split the k-sum.
__global__ void init_consts_kernel() {
    __shared__ double red[128];
    int e = blockIdx.x;
    int j = e / 11, d = e % 11;
    int k = threadIdx.x;

    double term = 0.0;
    if (k >= 1 && k <= 114) {
        double gd = (d == 0) ? 1.0 : 2.0 * cos(2.0 * PI_D * (double)k * (double)d / 512.0);
        term = 2.0 * gd * cos(2.0 * PI_D * (double)k * (double)j / 230.0);
    }
    red[threadIdx.x] = term;
    __syncthreads();
#pragma unroll
    for (int s = 64; s > 0; s >>= 1) {
        if (threadIdx.x < s) red[threadIdx.x] += red[threadIdx.x + s];
        __syncthreads();
    }
    if (threadIdx.x == 0) {
        double s = red[0];
        s += (d == 0) ? 1.0 : 2.0;                               // k = 0 bin
        double g115 = (d == 0) ? 1.0 : 2.0 * cos(2.0 * PI_D * 115.0 * (double)d / 512.0);
        s += ((j & 1) ? -1.0 : 1.0) * g115;                      // k = 115 Nyquist
        d_M[e] = s / 230.0;
    }
    if (e == 0 && threadIdx.x == 127) {
        double cr = 1.0, ci = 0.0;
        for (int p = 0; p < 10; p++) {
            double nr = cr * 0.4 - ci * 0.9;
            double ni = cr * 0.9 + ci * 0.4;
            cr = nr; ci = ni;
            d_x0[p]      = (float)nr;
            d_x0[10 + p] = (float)ni;
        }
    }
}

// Smith complex division with approx divides + __divsc3-style recovery.
// Fallback path only (wild frames); identical to R13's division.
__device__ __noinline__ void cdivf(float a, float b, float c, float d,
                                   float& outr, float& outi) {
    float re, im;
    if (fabsf(c) >= fabsf(d)) {
        float r     = __fdividef(d, c);
        float denom = __fmaf_rn(d, r, c);
        float inv   = rcpa(denom);
        re = __fmul_rn(__fmaf_rn(b, r, a), inv);
        im = __fmul_rn(__fmaf_rn(-a, r, b), inv);
    } else {
        float r     = __fdividef(c, d);
        float denom = __fmaf_rn(c, r, d);
        float inv   = rcpa(denom);
        re = __fmul_rn(__fmaf_rn(a, r, b), inv);
        im = __fmul_rn(__fmaf_rn(b, r, -a), inv);
    }
    if (isnan(re) && isnan(im)) {
        if ((c == 0.0f && d == 0.0f) && (!isnan(a) || !isnan(b))) {
            re = copysignf(INFINITY, c) * a;
            im = copysignf(INFINITY, c) * b;
        } else if ((isinf(a) || isinf(b)) && isfinite(c) && isfinite(d)) {
            float aa = copysignf(isinf(a) ? 1.0f : 0.0f, a);
            float bb = copysignf(isinf(b) ? 1.0f : 0.0f, b);
            re = INFINITY * __fadd_rn(__fmul_rn(aa, c), __fmul_rn(bb, d));
            im = INFINITY * __fsub_rn(__fmul_rn(bb, c), __fmul_rn(aa, d));
        } else if ((isinf(c) || isinf(d)) && isfinite(a) && isfinite(b)) {
            float cc = copysignf(isinf(c) ? 1.0f : 0.0f, c);
            float dd = copysignf(isinf(d) ? 1.0f : 0.0f, d);
            re = 0.0f * __fadd_rn(__fmul_rn(a, cc), __fmul_rn(b, dd));
            im = 0.0f * __fsub_rn(__fmul_rn(b, cc), __fmul_rn(a, dd));
        }
    }
    outr = re; outi = im;
}

// Fused kernel: two threads per frame. Even lane runs the fp64 front-end;
// DK: 5 roots/thread as 2 packed f32x2 pairs + 1 scalar. Packed naive
// division with scalar Smith fallback; warp-level fixpoint exit.
__global__ void __launch_bounds__(128, 7)
formant_kernel(const float* __restrict__ in, float* __restrict__ out) {
    __shared__ double sM[121];
    __shared__ float sX0[20];
    if (threadIdx.x < 121) sM[threadIdx.x] = d_M[threadIdx.x];
    if (threadIdx.x < 20)  sX0[threadIdx.x] = d_x0[threadIdx.x];
    __syncthreads();

    int gtid  = blockIdx.x * 128 + threadIdx.x;
    int frame = gtid >> 1;
    int half  = gtid & 1;                 // 0: roots 0-4, 1: roots 5-9
    int b = frame / T_DIM;
    int t = frame - b * T_DIM;
    const float* base = in + (size_t)b * (P_ORD * T_DIM) + t;

    // ======== FRONT-END (fp64, even lane only) ========
    float pc[11];
#pragma unroll
    for (int i = 0; i < 11; i++) pc[i] = 0.f;

    if (half == 0) {
        double A[11];
        A[0] = 1.0;
        {
            double a[10];
            a[0] = (double)base[0];
#pragma unroll
            for (int p = 1; p < 10; p++) {
                double k = (double)base[p * T_DIM];
                double na[10];
#pragma unroll
                for (int i = 0; i < p; i++) na[i] = a[i] + k * a[p - 1 - i];
#pragma unroll
                for (int i = 0; i < p; i++) a[i] = na[i];
                a[p] = k;
            }
#pragma unroll
            for (int i = 0; i < 10; i++) A[i + 1] = a[i];
        }

        double c[11];
#pragma unroll
        for (int d = 0; d < 11; d++) {
            double s = 0.0;
#pragma unroll
            for (int n = 0; n < 11 - d; n++) s = fma(A[n], A[n + d], s);
            c[d] = s;
        }

        double r[11];
#pragma unroll
        for (int j = 0; j < 11; j++) {
            double s = 0.0;
#pragma unroll
            for (int d = 0; d < 11; d++) s = fma(sM[j * 11 + d], c[d], s);
            r[j] = s;
        }

        pc[0] = 1.0f;
        {
            double a[10];
            double k0 = -r[1] / r[0];
            a[0] = k0;
            double err = r[0] * (1.0 - k0 * k0);
#pragma unroll
            for (int m = 1; m < 10; m++) {
                double acc = r[m + 1];
#pragma unroll
                for (int i = 0; i < m; i++) acc = fma(a[i], r[m - i], acc);
                double k = -acc / err;
                double na[10];
#pragma unroll
                for (int i = 0; i < m; i++) na[i] = a[i] + k * a[m - 1 - i];
#pragma unroll
                for (int i = 0; i < m; i++) a[i] = na[i];
                a[m] = k;
                err *= (1.0 - k * k);
            }
#pragma unroll
            for (int i = 0; i < 10; i++) pc[i + 1] = (float)a[i];
        }
    }
    // broadcast pc from even lane to its odd partner
#pragma unroll
    for (int i = 0; i < 11; i++) {
        float v = __shfl_xor_sync(FULLMASK, pc[i], 1);
        if (half) pc[i] = v;
    }

    // packed (splatted) coefficients for the paired Horner
    u64 pcs2[11];
#pragma unroll
    for (int i = 1; i < 11; i++) pcs2[i] = pk2(pc[i], pc[i]);
    const u64 eps2 = pk2(1e-12f, 1e-12f);

    // ======== DURAND-KERNER: 2 f32x2 pairs + 1 scalar root per thread ========
    float xr[5], xi[5];
#pragma unroll
    for (int i = 0; i < 5; i++) {
        xr[i] = sX0[half * 5 + i];
        xi[i] = sX0[10 + half * 5 + i];
    }

#pragma unroll 1
    for (int it = 0; it < 30; it++) {
        // fetch partner's current roots (10 shuffles)
        float pr[5], pimg[5];
#pragma unroll
        for (int j = 0; j < 5; j++) {
            pr[j]   = __shfl_xor_sync(FULLMASK, xr[j], 1);
            pimg[j] = __shfl_xor_sync(FULLMASK, xi[j], 1);
        }

        // pack own state: pair A = roots (0,1), pair B = roots (2,3); root 4 scalar
        u64 AX = pk2(xr[0], xr[1]), AY = pk2(xi[0], xi[1]);
        u64 BX = pk2(xr[2], xr[3]), BY = pk2(xi[2], xi[3]);
        float X4 = xr[4], Y4 = xi[4];

        // ---- Horner polyval (first step folded: y1 = x + pc[1]) ----
        u64 yrA = add2(AX, pcs2[1]), yiA = AY;
        u64 yrB = add2(BX, pcs2[1]), yiB = BY;
        float yr4 = __fadd_rn(X4, pc[1]), yi4 = Y4;
#pragma unroll
        for (int m = 2; m <= 10; m++) {
            u64 tA = fma2(mul2(yiA, AY), NEG1_2, fma2(yrA, AX, pcs2[m]));
            yiA = fma2(yrA, AY, mul2(yiA, AX));
            yrA = tA;
            u64 tB = fma2(mul2(yiB, BY), NEG1_2, fma2(yrB, BX, pcs2[m]));
            yiB = fma2(yrB, BY, mul2(yiB, BX));
            yrB = tB;
            float t4 = __fmaf_rn(yr4, X4, __fmaf_rn(-yi4, Y4, pc[m]));
            yi4 = __fmaf_rn(yr4, Y4, __fmul_rn(yi4, X4));
            yr4 = t4;
        }

        // ---- denominator product over all 10 roots, eye on own diagonal ----
        u64 drA = 0, diA = 0, drB = 0, diB = 0;
        float dr4 = 0.f, di4 = 0.f;
#pragma unroll
        for (int j = 0; j < 10; j++) {
            float R  = (j < 5) ? xr[j]     : pr[j - 5];
            float I  = (j < 5) ? xi[j]     : pimg[j - 5];
            u64 R2 = pk2(R, R), I2 = pk2(I, I);

            u64 erA = sub2(AX, R2);
            if (j == 0) erA = add2(erA, EYE_LO2);
            if (j == 1) erA = add2(erA, EYE_HI2);
            u64 eiA = sub2(AY, I2);

            u64 erB = sub2(BX, R2);
            if (j == 2) erB = add2(erB, EYE_LO2);
            if (j == 3) erB = add2(erB, EYE_HI2);
            u64 eiB = sub2(BY, I2);

            float er4 = __fsub_rn(X4, R);
            if (j == 4) er4 = __fadd_rn(er4, 1.f);
            float ei4 = __fsub_rn(Y4, I);

            if (j == 0) {
                drA = erA; diA = eiA;
                drB = erB; diB = eiB;
                dr4 = er4; di4 = ei4;
            } else {
                u64 tA = fma2(mul2(diA, eiA), NEG1_2, mul2(drA, erA));
                diA = fma2(drA, eiA, mul2(diA, erA));
                drA = tA;
                u64 tB = fma2(mul2(diB, eiB), NEG1_2, mul2(drB, erB));
                diB = fma2(drB, eiB, mul2(diB, erB));
                drB = tB;
                float t4 = __fmaf_rn(dr4, er4, -__fmul_rn(di4, ei4));
                di4 = __fmaf_rn(dr4, ei4, __fmul_rn(di4, er4));
                dr4 = t4;
            }
        }

        // ---- packed naive division q = y*conj(d)/|d|^2, Smith fallback ----
        u64 drAe = add2(drA, eps2);
        u64 drBe = add2(drB, eps2);
        float dr4e = __fadd_rn(dr4, 1e-12f);

        u64 d2A = fma2(diA, diA, mul2(drAe, drAe));
        u64 d2B = fma2(diB, diB, mul2(drBe, drBe));
        float d24 = __fmaf_rn(di4, di4, __fmul_rn(dr4e, dr4e));

        u64 invA = pk2(rcpa(lo2(d2A)), rcpa(hi2(d2A)));
        u64 invB = pk2(rcpa(lo2(d2B)), rcpa(hi2(d2B)));
        float inv4 = rcpa(d24);

        u64 qrA = mul2(fma2(yiA, diA, mul2(yrA, drAe)), invA);
        u64 qiA = mul2(fma2(mul2(yrA, diA), NEG1_2, mul2(yiA, drAe)), invA);
        u64 qrB = mul2(fma2(yiB, diB, mul2(yrB, drBe)), invB);
        u64 qiB = mul2(fma2(mul2(yrB, diB), NEG1_2, mul2(yiB, drBe)), invB);
        float qr4 = __fmul_rn(__fmaf_rn(yi4, di4, __fmul_rn(yr4, dr4e)), inv4);
        float qi4 = __fmul_rn(__fmaf_rn(yi4, dr4e, -__fmul_rn(yr4, di4)), inv4);

        float qrS[5] = { lo2(qrA), hi2(qrA), lo2(qrB), hi2(qrB), qr4 };
        float qiS[5] = { lo2(qiA), hi2(qiA), lo2(qiB), hi2(qiB), qi4 };
        float d2S[5] = { lo2(d2A), hi2(d2A), lo2(d2B), hi2(d2B), d24 };
        float yrS[5] = { lo2(yrA), hi2(yrA), lo2(yrB), hi2(yrB), yr4 };
        float yiS[5] = { lo2(yiA), hi2(yiA), lo2(yiB), hi2(yiB), yi4 };
        float drS[5] = { lo2(drAe), hi2(drAe), lo2(drBe), hi2(drBe), dr4e };
        float diS[5] = { lo2(diA), hi2(diA), lo2(diB), hi2(diB), di4 };

        bool same = true;
#pragma unroll
        for (int i = 0; i < 5; i++) {
            float qr = qrS[i], qi = qiS[i];
            // Fallback when naive saturated: q non-finite (NaN fails <) or
            // |d|^2 overflowed (naive silently returns ~0 there, Smith doesn't).
            if (!(fabsf(qr) < 1e38f) || !(fabsf(qi) < 1e38f)
                || !(d2S[i] < 3.4e38f)) {
                cdivf(yrS[i], yiS[i], drS[i], diS[i], qr, qi);
            }
            float nx = __fsub_rn(xr[i], qr);
            float ny = __fsub_rn(xi[i], qi);
            same = same && (__float_as_int(nx) == __float_as_int(xr[i]))
                        && (__float_as_int(ny) == __float_as_int(xi[i]));
            xr[i] = nx; xi[i] = ny;
        }
        // Warp-level bitwise fixpoint -> remaining iterations are no-ops.
        if (__all_sync(FULLMASK, same)) break;
    }

    // ---- roots -> formants, exchange, sort, write (even lane) ----
    float f5[5];
#pragma unroll
    for (int i = 0; i < 5; i++) {
        float fr = atan2f(xi[i], xr[i]) * (10000.0f / (2.0f * (float)PI_D));
        bool valid = (xi[i] > 0.f) && (fr > 50.0f) && (fr < 4950.0f);
        f5[i] = valid ? fr : 10000.0f;
    }
    float pf[5];
#pragma unroll
    for (int j = 0; j < 5; j++) pf[j] = __shfl_xor_sync(FULLMASK, f5[j], 1);

    float f[10];
#pragma unroll
    for (int j = 0; j < 5; j++) {
        f[j]     = half ? pf[j] : f5[j];
        f[5 + j] = half ? f5[j] : pf[j];
    }
#pragma unroll
    for (int pass = 0; pass < 9; pass++) {
#pragma unroll
        for (int i = 0; i < 9; i++) {
            float lo = fminf(f[i], f[i + 1]);
            float hi = fmaxf(f[i], f[i + 1]);
            f[i] = lo; f[i + 1] = hi;
        }
    }

    if (half == 0) {
        float* ob = out + (size_t)b * (4 * T_DIM) + t;
#pragma unroll
        for (int q = 0; q < 4; q++)
            ob[q * T_DIM] = 2.0f * f[q] / 11025.0f - 1.0f;
    }
}

extern "C" void kernel_launch(void* const* d_in, const int* in_sizes, int n_in,
                              void* d_out, int out_size) {
    const float* in = (const float*)d_in[0];
    float* out = (float*)d_out;
    (void)in_sizes; (void)n_in; (void)out_size;

    init_consts_kernel<<<121, 128>>>();
    formant_kernel<<<(NFRAMES * 2) / 128, 128>>>(in, out);
}

// round 17
// speedup vs baseline: 1.3448x; 1.0183x over previous
#include <cuda_runtime.h>
#include <math.h>

#define B_DIM 64
#define T_DIM 1000
#define P_ORD 10
#define NFRAMES (B_DIM * T_DIM)
#define PI_D 3.14159265358979323846
#define FULLMASK 0xffffffffu

__device__ double d_M[121];
__device__ float d_x0[20];

// ---- packed f32x2 helpers (sm_100+) ----
typedef unsigned long long u64;
__device__ __forceinline__ u64 pk2(float lo, float hi) {
    u64 r; asm("mov.b64 %0, {%1, %2};" : "=l"(r) : "f"(lo), "f"(hi)); return r;
}
__device__ __forceinline__ u64 add2(u64 a, u64 b) {
    u64 r; asm("add.rn.f32x2 %0, %1, %2;" : "=l"(r) : "l"(a), "l"(b)); return r;
}
__device__ __forceinline__ u64 mul2(u64 a, u64 b) {
    u64 r; asm("mul.rn.f32x2 %0, %1, %2;" : "=l"(r) : "l"(a), "l"(b)); return r;
}
__device__ __forceinline__ u64 fma2(u64 a, u64 b, u64 c) {
    u64 r; asm("fma.rn.f32x2 %0, %1, %2, %3;" : "=l"(r) : "l"(a), "l"(b), "l"(c)); return r;
}
__device__ __forceinline__ float lo2(u64 v) { return __uint_as_float((unsigned)v); }
__device__ __forceinline__ float hi2(u64 v) { return __uint_as_float((unsigned)(v >> 32)); }
__device__ __forceinline__ float rcpa(float x) {
    float r; asm("rcp.approx.f32 %0, %1;" : "=f"(r) : "f"(x)); return r;
}
#define NEG1_2  0xBF800000BF800000ULL   /* (-1,-1) */
#define EYE_LO2 0x000000003F800000ULL   /* (1, 0)  */
#define EYE_HI2 0x3F80000000000000ULL   /* (0, 1)  */
// exact subtraction a-b via single-rounded fma(b, -1, a)
__device__ __forceinline__ u64 sub2(u64 a, u64 b) { return fma2(b, NEG1_2, a); }

// Parallel init: one block per matrix entry (j,d); threads split the k-sum.
__global__ void init_consts_kernel() {
    __shared__ double red[128];
    int e = blockIdx.x;
    int j = e / 11, d = e % 11;
    int k = threadIdx.x;

    double term = 0.0;
    if (k >= 1 && k <= 114) {
        double gd = (d == 0) ? 1.0 : 2.0 * cos(2.0 * PI_D * (double)k * (double)d / 512.0);
        term = 2.0 * gd * cos(2.0 * PI_D * (double)k * (double)j / 230.0);
    }
    red[threadIdx.x] = term;
    __syncthreads();
#pragma unroll
    for (int s = 64; s > 0; s >>= 1) {
        if (threadIdx.x < s) red[threadIdx.x] += red[threadIdx.x + s];
        __syncthreads();
    }
    if (threadIdx.x == 0) {
        double s = red[0];
        s += (d == 0) ? 1.0 : 2.0;                               // k = 0 bin
        double g115 = (d == 0) ? 1.0 : 2.0 * cos(2.0 * PI_D * 115.0 * (double)d / 512.0);
        s += ((j & 1) ? -1.0 : 1.0) * g115;                      // k = 115 Nyquist
        d_M[e] = s / 230.0;
    }
    if (e == 0 && threadIdx.x == 127) {
        double cr = 1.0, ci = 0.0;
        for (int p = 0; p < 10; p++) {
            double nr = cr * 0.4 - ci * 0.9;
            double ni = cr * 0.9 + ci * 0.4;
            cr = nr; ci = ni;
            d_x0[p]      = (float)nr;
            d_x0[10 + p] = (float)ni;
        }
    }
}

// Smith complex division with approx divides + __divsc3-style recovery.
// Fallback path only (wild frames); identical to R13's division.
__device__ __noinline__ void cdivf(float a, float b, float c, float d,
                                   float& outr, float& outi) {
    float re, im;
    if (fabsf(c) >= fabsf(d)) {
        float r     = __fdividef(d, c);
        float denom = __fmaf_rn(d, r, c);
        float inv   = rcpa(denom);
        re = __fmul_rn(__fmaf_rn(b, r, a), inv);
        im = __fmul_rn(__fmaf_rn(-a, r, b), inv);
    } else {
        float r     = __fdividef(c, d);
        float denom = __fmaf_rn(c, r, d);
        float inv   = rcpa(denom);
        re = __fmul_rn(__fmaf_rn(a, r, b), inv);
        im = __fmul_rn(__fmaf_rn(b, r, -a), inv);
    }
    if (isnan(re) && isnan(im)) {
        if ((c == 0.0f && d == 0.0f) && (!isnan(a) || !isnan(b))) {
            re = copysignf(INFINITY, c) * a;
            im = copysignf(INFINITY, c) * b;
        } else if ((isinf(a) || isinf(b)) && isfinite(c) && isfinite(d)) {
            float aa = copysignf(isinf(a) ? 1.0f : 0.0f, a);
            float bb = copysignf(isinf(b) ? 1.0f : 0.0f, b);
            re = INFINITY * __fadd_rn(__fmul_rn(aa, c), __fmul_rn(bb, d));
            im = INFINITY * __fsub_rn(__fmul_rn(bb, c), __fmul_rn(aa, d));
        } else if ((isinf(c) || isinf(d)) && isfinite(a) && isfinite(b)) {
            float cc = copysignf(isinf(c) ? 1.0f : 0.0f, c);
            float dd = copysignf(isinf(d) ? 1.0f : 0.0f, d);
            re = 0.0f * __fadd_rn(__fmul_rn(a, cc), __fmul_rn(b, dd));
            im = 0.0f * __fsub_rn(__fmul_rn(b, cc), __fmul_rn(a, dd));
        }
    }
    outr = re; outi = im;
}

// Fused kernel: two threads per frame. Even lane runs the fp64 front-end;
// DK: 5 roots/thread as 2 packed f32x2 pairs + 1 scalar. Packed naive
// division (no staging arrays) with scalar Smith fallback; warp-level exit.
__global__ void __launch_bounds__(128, 7)
formant_kernel(const float* __restrict__ in, float* __restrict__ out) {
    __shared__ double sM[121];
    __shared__ float sX0[20];
    if (threadIdx.x < 121) sM[threadIdx.x] = d_M[threadIdx.x];
    if (threadIdx.x < 20)  sX0[threadIdx.x] = d_x0[threadIdx.x];
    __syncthreads();

    int gtid  = blockIdx.x * 128 + threadIdx.x;
    int frame = gtid >> 1;
    int half  = gtid & 1;                 // 0: roots 0-4, 1: roots 5-9
    int b = frame / T_DIM;
    int t = frame - b * T_DIM;
    const float* base = in + (size_t)b * (P_ORD * T_DIM) + t;

    // ======== FRONT-END (fp64, even lane only) ========
    float pc[11];
#pragma unroll
    for (int i = 0; i < 11; i++) pc[i] = 0.f;

    if (half == 0) {
        double A[11];
        A[0] = 1.0;
        {
            double a[10];
            a[0] = (double)base[0];
#pragma unroll
            for (int p = 1; p < 10; p++) {
                double k = (double)base[p * T_DIM];
                double na[10];
#pragma unroll
                for (int i = 0; i < p; i++) na[i] = a[i] + k * a[p - 1 - i];
#pragma unroll
                for (int i = 0; i < p; i++) a[i] = na[i];
                a[p] = k;
            }
#pragma unroll
            for (int i = 0; i < 10; i++) A[i + 1] = a[i];
        }

        double c[11];
#pragma unroll
        for (int d = 0; d < 11; d++) {
            double s = 0.0;
#pragma unroll
            for (int n = 0; n < 11 - d; n++) s = fma(A[n], A[n + d], s);
            c[d] = s;
        }

        double r[11];
#pragma unroll
        for (int j = 0; j < 11; j++) {
            double s = 0.0;
#pragma unroll
            for (int d = 0; d < 11; d++) s = fma(sM[j * 11 + d], c[d], s);
            r[j] = s;
        }

        pc[0] = 1.0f;
        {
            double a[10];
            double k0 = -r[1] / r[0];
            a[0] = k0;
            double err = r[0] * (1.0 - k0 * k0);
#pragma unroll
            for (int m = 1; m < 10; m++) {
                double acc = r[m + 1];
#pragma unroll
                for (int i = 0; i < m; i++) acc = fma(a[i], r[m - i], acc);
                double k = -acc / err;
                double na[10];
#pragma unroll
                for (int i = 0; i < m; i++) na[i] = a[i] + k * a[m - 1 - i];
#pragma unroll
                for (int i = 0; i < m; i++) a[i] = na[i];
                a[m] = k;
                err *= (1.0 - k * k);
            }
#pragma unroll
            for (int i = 0; i < 10; i++) pc[i + 1] = (float)a[i];
        }
    }
    // broadcast pc from even lane to its odd partner
#pragma unroll
    for (int i = 0; i < 11; i++) {
        float v = __shfl_xor_sync(FULLMASK, pc[i], 1);
        if (half) pc[i] = v;
    }

    // packed (splatted) coefficients for the paired Horner
    u64 pcs2[11];
#pragma unroll
    for (int i = 1; i < 11; i++) pcs2[i] = pk2(pc[i], pc[i]);
    const u64 eps2 = pk2(1e-12f, 1e-12f);

    // ======== DURAND-KERNER: 2 f32x2 pairs + 1 scalar root per thread ========
    float xr[5], xi[5];
#pragma unroll
    for (int i = 0; i < 5; i++) {
        xr[i] = sX0[half * 5 + i];
        xi[i] = sX0[10 + half * 5 + i];
    }

#pragma unroll 1
    for (int it = 0; it < 30; it++) {
        // fetch partner's current roots (10 shuffles)
        float pr[5], pimg[5];
#pragma unroll
        for (int j = 0; j < 5; j++) {
            pr[j]   = __shfl_xor_sync(FULLMASK, xr[j], 1);
            pimg[j] = __shfl_xor_sync(FULLMASK, xi[j], 1);
        }

        // pack own state: pair A = roots (0,1), pair B = roots (2,3); root 4 scalar
        u64 AX = pk2(xr[0], xr[1]), AY = pk2(xi[0], xi[1]);
        u64 BX = pk2(xr[2], xr[3]), BY = pk2(xi[2], xi[3]);
        float X4 = xr[4], Y4 = xi[4];

        // ---- Horner polyval (first step folded: y1 = x + pc[1]) ----
        u64 yrA = add2(AX, pcs2[1]), yiA = AY;
        u64 yrB = add2(BX, pcs2[1]), yiB = BY;
        float yr4 = __fadd_rn(X4, pc[1]), yi4 = Y4;
#pragma unroll
        for (int m = 2; m <= 10; m++) {
            u64 tA = fma2(mul2(yiA, AY), NEG1_2, fma2(yrA, AX, pcs2[m]));
            yiA = fma2(yrA, AY, mul2(yiA, AX));
            yrA = tA;
            u64 tB = fma2(mul2(yiB, BY), NEG1_2, fma2(yrB, BX, pcs2[m]));
            yiB = fma2(yrB, BY, mul2(yiB, BX));
            yrB = tB;
            float t4 = __fmaf_rn(yr4, X4, __fmaf_rn(-yi4, Y4, pc[m]));
            yi4 = __fmaf_rn(yr4, Y4, __fmul_rn(yi4, X4));
            yr4 = t4;
        }

        // ---- denominator product over all 10 roots, eye on own diagonal ----
        u64 drA = 0, diA = 0, drB = 0, diB = 0;
        float dr4 = 0.f, di4 = 0.f;
#pragma unroll
        for (int j = 0; j < 10; j++) {
            float R  = (j < 5) ? xr[j]     : pr[j - 5];
            float I  = (j < 5) ? xi[j]     : pimg[j - 5];
            u64 R2 = pk2(R, R), I2 = pk2(I, I);

            u64 erA = sub2(AX, R2);
            if (j == 0) erA = add2(erA, EYE_LO2);
            if (j == 1) erA = add2(erA, EYE_HI2);
            u64 eiA = sub2(AY, I2);

            u64 erB = sub2(BX, R2);
            if (j == 2) erB = add2(erB, EYE_LO2);
            if (j == 3) erB = add2(erB, EYE_HI2);
            u64 eiB = sub2(BY, I2);

            float er4 = __fsub_rn(X4, R);
            if (j == 4) er4 = __fadd_rn(er4, 1.f);
            float ei4 = __fsub_rn(Y4, I);

            if (j == 0) {
                drA = erA; diA = eiA;
                drB = erB; diB = eiB;
                dr4 = er4; di4 = ei4;
            } else {
                u64 tA = fma2(mul2(diA, eiA), NEG1_2, mul2(drA, erA));
                diA = fma2(drA, eiA, mul2(diA, erA));
                drA = tA;
                u64 tB = fma2(mul2(diB, eiB), NEG1_2, mul2(drB, erB));
                diB = fma2(drB, eiB, mul2(diB, erB));
                drB = tB;
                float t4 = __fmaf_rn(dr4, er4, -__fmul_rn(di4, ei4));
                di4 = __fmaf_rn(dr4, ei4, __fmul_rn(di4, er4));
                dr4 = t4;
            }
        }

        // ---- packed naive division + fallback + update, per pair (no arrays) ----
        bool same = true;

        {   // pair A (roots 0,1)
            u64 dre = add2(drA, eps2);
            u64 d2  = fma2(diA, diA, mul2(dre, dre));
            u64 inv = pk2(rcpa(lo2(d2)), rcpa(hi2(d2)));
            u64 qr  = mul2(fma2(yiA, diA, mul2(yrA, dre)), inv);
            u64 qi  = mul2(fma2(mul2(yrA, diA), NEG1_2, mul2(yiA, dre)), inv);
            float q0r = lo2(qr), q0i = lo2(qi), q1r = hi2(qr), q1i = hi2(qi);
            if (!(fabsf(q0r) < 1e38f) || !(fabsf(q0i) < 1e38f) || !(lo2(d2) < 3.4e38f))
                cdivf(lo2(yrA), lo2(yiA), lo2(dre), lo2(diA), q0r, q0i);
            if (!(fabsf(q1r) < 1e38f) || !(fabsf(q1i) < 1e38f) || !(hi2(d2) < 3.4e38f))
                cdivf(hi2(yrA), hi2(yiA), hi2(dre), hi2(diA), q1r, q1i);
            float nx0 = __fsub_rn(xr[0], q0r), ny0 = __fsub_rn(xi[0], q0i);
            float nx1 = __fsub_rn(xr[1], q1r), ny1 = __fsub_rn(xi[1], q1i);
            same = same && (__float_as_int(nx0) == __float_as_int(xr[0]))
                        && (__float_as_int(ny0) == __float_as_int(xi[0]))
                        && (__float_as_int(nx1) == __float_as_int(xr[1]))
                        && (__float_as_int(ny1) == __float_as_int(xi[1]));
            xr[0] = nx0; xi[0] = ny0; xr[1] = nx1; xi[1] = ny1;
        }
        {   // pair B (roots 2,3)
            u64 dre = add2(drB, eps2);
            u64 d2  = fma2(diB, diB, mul2(dre, dre));
            u64 inv = pk2(rcpa(lo2(d2)), rcpa(hi2(d2)));
            u64 qr  = mul2(fma2(yiB, diB, mul2(yrB, dre)), inv);
            u64 qi  = mul2(fma2(mul2(yrB, diB), NEG1_2, mul2(yiB, dre)), inv);
            float q0r = lo2(qr), q0i = lo2(qi), q1r = hi2(qr), q1i = hi2(qi);
            if (!(fabsf(q0r) < 1e38f) || !(fabsf(q0i) < 1e38f) || !(lo2(d2) < 3.4e38f))
                cdivf(lo2(yrB), lo2(yiB), lo2(dre), lo2(diB), q0r, q0i);
            if (!(fabsf(q1r) < 1e38f) || !(fabsf(q1i) < 1e38f) || !(hi2(d2) < 3.4e38f))
                cdivf(hi2(yrB), hi2(yiB), hi2(dre), hi2(diB), q1r, q1i);
            float nx0 = __fsub_rn(xr[2], q0r), ny0 = __fsub_rn(xi[2], q0i);
            float nx1 = __fsub_rn(xr[3], q1r), ny1 = __fsub_rn(xi[3], q1i);
            same = same && (__float_as_int(nx0) == __float_as_int(xr[2]))
                        && (__float_as_int(ny0) == __float_as_int(xi[2]))
                        && (__float_as_int(nx1) == __float_as_int(xr[3]))
                        && (__float_as_int(ny1) == __float_as_int(xi[3]));
            xr[2] = nx0; xi[2] = ny0; xr[3] = nx1; xi[3] = ny1;
        }
        {   // scalar root 4
            float dre = __fadd_rn(dr4, 1e-12f);
            float d2  = __fmaf_rn(di4, di4, __fmul_rn(dre, dre));
            float inv = rcpa(d2);
            float qr = __fmul_rn(__fmaf_rn(yi4, di4, __fmul_rn(yr4, dre)), inv);
            float qi = __fmul_rn(__fmaf_rn(yi4, dre, -__fmul_rn(yr4, di4)), inv);
            if (!(fabsf(qr) < 1e38f) || !(fabsf(qi) < 1e38f) || !(d2 < 3.4e38f))
                cdivf(yr4, yi4, dre, di4, qr, qi);
            float nx = __fsub_rn(xr[4], qr), ny = __fsub_rn(xi[4], qi);
            same = same && (__float_as_int(nx) == __float_as_int(xr[4]))
                        && (__float_as_int(ny) == __float_as_int(xi[4]));
            xr[4] = nx; xi[4] = ny;
        }

        // Warp-level bitwise fixpoint -> remaining iterations are no-ops.
        if (__all_sync(FULLMASK, same)) break;
    }

    // ---- roots -> formants, exchange, sort, write (even lane) ----
    float f5[5];
#pragma unroll
    for (int i = 0; i < 5; i++) {
        float fr = atan2f(xi[i], xr[i]) * (10000.0f / (2.0f * (float)PI_D));
        bool valid = (xi[i] > 0.f) && (fr > 50.0f) && (fr < 4950.0f);
        f5[i] = valid ? fr : 10000.0f;
    }
    float pf[5];
#pragma unroll
    for (int j = 0; j < 5; j++) pf[j] = __shfl_xor_sync(FULLMASK, f5[j], 1);

    float f[10];
#pragma unroll
    for (int j = 0; j < 5; j++) {
        f[j]     = half ? pf[j] : f5[j];
        f[5 + j] = half ? f5[j] : pf[j];
    }
#pragma unroll
    for (int pass = 0; pass < 9; pass++) {
#pragma unroll
        for (int i = 0; i < 9; i++) {
            float lo = fminf(f[i], f[i + 1]);
            float hi = fmaxf(f[i], f[i + 1]);
            f[i] = lo; f[i + 1] = hi;
        }
    }

    if (half == 0) {
        float* ob = out + (size_t)b * (4 * T_DIM) + t;
#pragma unroll
        for (int q = 0; q < 4; q++)
            ob[q * T_DIM] = 2.0f * f[q] / 11025.0f - 1.0f;
    }
}

extern "C" void kernel_launch(void* const* d_in, const int* in_sizes, int n_in,
                              void* d_out, int out_size) {
    const float* in = (const float*)d_in[0];
    float* out = (float*)d_out;
    (void)in_sizes; (void)n_in; (void)out_size;

    init_consts_kernel<<<121, 128>>>();
    formant_kernel<<<(NFRAMES * 2) / 128, 128>>>(in, out);
}